// round 14
// baseline (speedup 1.0000x reference)
#include <cuda_runtime.h>
#include <cuda_fp16.h>
#include <cstdint>

// ---------------------------------------------------------------------------
// MHA.  R14: GEMMs = 64x64 warp tiles (1.0 LDS/mma) in 128-thread CTAs with
// 2 CTAs/SM (two barrier domains, 8 warps/SM) — fixes R13's occupancy loss.
// Attention + prepass = R12 (best known).
// ---------------------------------------------------------------------------

#define SEQ     2048
#define BATCH   2
#define NH      16
#define HD      64
#define HID     1024
#define HID3    3072
#define MROWS   (BATCH * SEQ)   // 4096

__device__ __half g_Ah[MROWS * HID];
__device__ __half g_Wf[HID * HID3];
__device__ __half g_Woh[HID * HID];
__device__ float  g_bf[HID3];
__device__ __half g_QKVh[(size_t)MROWS * HID3];
__device__ __half g_Oh[MROWS * HID];

// ------------------------------ helpers ------------------------------------
__device__ __forceinline__ uint32_t packh2(float a, float b) {
    __half2 h = __floats2half2_rn(a, b);
    return *(uint32_t*)&h;
}

__device__ __forceinline__ uint32_t prmt(uint32_t a, uint32_t b, uint32_t s) {
    uint32_t d;
    asm("prmt.b32 %0, %1, %2, %3;" : "=r"(d) : "r"(a), "r"(b), "r"(s));
    return d;
}

__device__ __forceinline__ void mma_f16(float* d, const uint32_t* a,
                                        uint32_t b0, uint32_t b1) {
    asm volatile(
        "mma.sync.aligned.m16n8k16.row.col.f32.f16.f16.f32 "
        "{%0,%1,%2,%3}, {%4,%5,%6,%7}, {%8,%9}, {%0,%1,%2,%3};"
        : "+f"(d[0]), "+f"(d[1]), "+f"(d[2]), "+f"(d[3])
        : "r"(a[0]), "r"(a[1]), "r"(a[2]), "r"(a[3]), "r"(b0), "r"(b1));
}

// ============================ pre-pass ======================================
__global__ void cvt16(const float* __restrict__ src, __half* __restrict__ dst) {
    size_t i = ((size_t)blockIdx.x * 256 + threadIdx.x) * 8;
    float4 a = *(const float4*)(src + i);
    float4 b = *(const float4*)(src + i + 4);
    uint4 v = {packh2(a.x, a.y), packh2(a.z, a.w),
               packh2(b.x, b.y), packh2(b.z, b.w)};
    *(uint4*)(dst + i) = v;
}

__global__ void fuseW(const float* __restrict__ Wq, const float* __restrict__ Wkv,
                      const float* __restrict__ bq, const float* __restrict__ bkv,
                      __half* __restrict__ Wf, float* __restrict__ bf) {
    int gid = blockIdx.x * 256 + threadIdx.x;
    size_t e = (size_t)gid * 8;
    int r = (int)(e / HID3), c = (int)(e % HID3);
    const float* src = (c < HID) ? Wq + (size_t)r * HID + c
                                 : Wkv + (size_t)r * (2 * HID) + (c - HID);
    float4 a = *(const float4*)src;
    float4 b = *(const float4*)(src + 4);
    uint4 v = {packh2(a.x, a.y), packh2(a.z, a.w),
               packh2(b.x, b.y), packh2(b.z, b.w)};
    *(uint4*)(Wf + e) = v;
    if (gid < HID3 / 8) {
        int cb = gid * 8;
        const float* sb = (cb < HID) ? bq + cb : bkv + (cb - HID);
        *(float4*)(bf + cb)     = *(const float4*)sb;
        *(float4*)(bf + cb + 4) = *(const float4*)(sb + 4);
    }
}

// ============================ fp16 GEMM =====================================
// C[M,N] = A[M,K] @ B[K,N] + bias[N].  CTA tile 128x128, BK=64, 128 threads,
// 4 warps (2M x 2N), warp tile 64x64 (mt=4, nt=8), m16n8k16, 2 CTAs/SM.
// A smem [m][k2] pad GA=36; B smem k-pair-interleaved [k2][n] pad GB=136.
// Double-buffered, single barrier per chunk.
#define GA 36
#define GB 136
#define GEMM_SMEM ((2 * (128 * GA + 32 * GB)) * 4)   // 71680 bytes

__global__ __launch_bounds__(128, 2) void gemm_f16(
    const __half* __restrict__ A, int lda,
    const __half* __restrict__ B, int ldb,
    const float* __restrict__ bias,
    void* __restrict__ Cout, int ldc, int K, int fp16out)
{
    extern __shared__ uint32_t smg[];
    uint32_t* Asm = smg;                 // [2][128*GA]
    uint32_t* Bsm = smg + 2 * 128 * GA;  // [2][32*GB]

    const int tid  = threadIdx.x;
    const int wid  = tid >> 5, lane = tid & 31;
    const int g    = lane >> 2, t = lane & 3;
    const int wr   = wid & 1,  wc = wid >> 1;      // each 0..1
    const int row0 = blockIdx.y * 128;
    const int col0 = blockIdx.x * 128;

    // staging maps (128 threads)
    const int ar  = tid;                         // A: one row per thread
    const int kp  = tid >> 2;                    // B: k-pair row (0..31)
    const int ng  = (tid & 3) * 32;              // B: n cols ng..ng+31
    const int rot = tid & 3;                     // STS bank rotation

    const __half* Ag = A + (size_t)row0 * lda;
    const __half* Bg = B + col0;

    uint4 ra[4], rbx[2], rby[2];                 // A 64B... A=8 uint4 handled in 2 halves
    uint4 ra2[4];
    const int NT = K >> 6;

    // ---- prologue: load + stage chunk 0 ----
    #pragma unroll
    for (int i = 0; i < 4; i++) {
        ra[i]  = *(const uint4*)(Ag + (size_t)ar * lda + 8 * i);
        ra2[i] = *(const uint4*)(Ag + (size_t)ar * lda + 32 + 8 * i);
    }
    rbx[0] = *(const uint4*)(Bg + (size_t)(2 * kp) * ldb + ng);
    rbx[1] = *(const uint4*)(Bg + (size_t)(2 * kp) * ldb + ng + 8);
    rby[0] = *(const uint4*)(Bg + (size_t)(2 * kp + 1) * ldb + ng);
    rby[1] = *(const uint4*)(Bg + (size_t)(2 * kp + 1) * ldb + ng + 8);
    uint4 rbx2 = *(const uint4*)(Bg + (size_t)(2 * kp) * ldb + ng + 16);
    uint4 rbx3 = *(const uint4*)(Bg + (size_t)(2 * kp) * ldb + ng + 24);
    uint4 rby2 = *(const uint4*)(Bg + (size_t)(2 * kp + 1) * ldb + ng + 16);
    uint4 rby3 = *(const uint4*)(Bg + (size_t)(2 * kp + 1) * ldb + ng + 24);
    {
        #pragma unroll
        for (int i = 0; i < 4; i++) {
            *(uint4*)&Asm[ar * GA + 4 * i]      = ra[i];
            *(uint4*)&Asm[ar * GA + 16 + 4 * i] = ra2[i];
        }
        uint32_t xa[16] = {rbx[0].x, rbx[0].y, rbx[0].z, rbx[0].w,
                           rbx[1].x, rbx[1].y, rbx[1].z, rbx[1].w,
                           rbx2.x, rbx2.y, rbx2.z, rbx2.w,
                           rbx3.x, rbx3.y, rbx3.z, rbx3.w};
        uint32_t ya[16] = {rby[0].x, rby[0].y, rby[0].z, rby[0].w,
                           rby[1].x, rby[1].y, rby[1].z, rby[1].w,
                           rby2.x, rby2.y, rby2.z, rby2.w,
                           rby3.x, rby3.y, rby3.z, rby3.w};
        uint32_t z[32];
        #pragma unroll
        for (int i = 0; i < 16; i++) {
            z[2 * i + 0] = prmt(xa[i], ya[i], 0x5410);
            z[2 * i + 1] = prmt(xa[i], ya[i], 0x7632);
        }
        #pragma unroll
        for (int j = 0; j < 8; j++) {
            const int jj = (j + rot) & 7;
            *(uint4*)&Bsm[kp * GB + ng + 4 * jj] = *(uint4*)&z[4 * jj];
        }
    }
    __syncthreads();

    float acc[4][8][4] = {};

    for (int kt = 0; kt < NT; kt++) {
        uint4 nbx2, nbx3, nby2, nby3;
        if (kt + 1 < NT) {
            const int kc = (kt + 1) * 64;
            #pragma unroll
            for (int i = 0; i < 4; i++) {
                ra[i]  = *(const uint4*)(Ag + (size_t)ar * lda + kc + 8 * i);
                ra2[i] = *(const uint4*)(Ag + (size_t)ar * lda + kc + 32 + 8 * i);
            }
            const __half* s0 = Bg + (size_t)(kc + 2 * kp) * ldb + ng;
            const __half* s1 = s0 + ldb;
            rbx[0] = *(const uint4*)s0; rbx[1] = *(const uint4*)(s0 + 8);
            nbx2 = *(const uint4*)(s0 + 16); nbx3 = *(const uint4*)(s0 + 24);
            rby[0] = *(const uint4*)s1; rby[1] = *(const uint4*)(s1 + 8);
            nby2 = *(const uint4*)(s1 + 16); nby3 = *(const uint4*)(s1 + 24);
        }

        const uint32_t* Ac = Asm + (kt & 1) * 128 * GA;
        const uint32_t* Bc = Bsm + (kt & 1) * 32 * GB;

        #pragma unroll
        for (int ks = 0; ks < 4; ks++) {
            uint32_t af[4][4];
            #pragma unroll
            for (int mt = 0; mt < 4; mt++) {
                const uint32_t* ap = Ac + (wr * 64 + mt * 16) * GA + ks * 8;
                af[mt][0] = ap[ g      * GA + t    ];
                af[mt][1] = ap[(g + 8) * GA + t    ];
                af[mt][2] = ap[ g      * GA + t + 4];
                af[mt][3] = ap[(g + 8) * GA + t + 4];
            }
            #pragma unroll
            for (int nt = 0; nt < 8; nt++) {
                const int ncol = wc * 64 + nt * 8 + g;
                uint32_t b0 = Bc[(ks * 8 + t    ) * GB + ncol];
                uint32_t b1 = Bc[(ks * 8 + t + 4) * GB + ncol];
                #pragma unroll
                for (int mt = 0; mt < 4; mt++)
                    mma_f16(acc[mt][nt], af[mt], b0, b1);
            }
        }

        if (kt + 1 < NT) {
            // single-barrier double buffer: all warps passed barrier(kt-1)
            uint32_t* Ad = Asm + ((kt + 1) & 1) * 128 * GA;
            uint32_t* Bd = Bsm + ((kt + 1) & 1) * 32 * GB;
            #pragma unroll
            for (int i = 0; i < 4; i++) {
                *(uint4*)&Ad[ar * GA + 4 * i]      = ra[i];
                *(uint4*)&Ad[ar * GA + 16 + 4 * i] = ra2[i];
            }
            uint32_t xa[16] = {rbx[0].x, rbx[0].y, rbx[0].z, rbx[0].w,
                               rbx[1].x, rbx[1].y, rbx[1].z, rbx[1].w,
                               nbx2.x, nbx2.y, nbx2.z, nbx2.w,
                               nbx3.x, nbx3.y, nbx3.z, nbx3.w};
            uint32_t ya[16] = {rby[0].x, rby[0].y, rby[0].z, rby[0].w,
                               rby[1].x, rby[1].y, rby[1].z, rby[1].w,
                               nby2.x, nby2.y, nby2.z, nby2.w,
                               nby3.x, nby3.y, nby3.z, nby3.w};
            uint32_t z[32];
            #pragma unroll
            for (int i = 0; i < 16; i++) {
                z[2 * i + 0] = prmt(xa[i], ya[i], 0x5410);
                z[2 * i + 1] = prmt(xa[i], ya[i], 0x7632);
            }
            #pragma unroll
            for (int j = 0; j < 8; j++) {
                const int jj = (j + rot) & 7;
                *(uint4*)&Bd[kp * GB + ng + 4 * jj] = *(uint4*)&z[4 * jj];
            }
            __syncthreads();
        }
    }

    // ---- epilogue ----
    if (fp16out) {
        __half* Ch = (__half*)Cout;
        #pragma unroll
        for (int mt = 0; mt < 4; mt++) {
            const int row = row0 + wr * 64 + mt * 16 + g;
            #pragma unroll
            for (int nt = 0; nt < 8; nt++) {
                const int col = col0 + wc * 64 + nt * 8 + 2 * t;
                float2 bb = *(const float2*)&bias[col];
                *(uint32_t*)&Ch[(size_t)row * ldc + col] =
                    packh2(acc[mt][nt][0] + bb.x, acc[mt][nt][1] + bb.y);
                *(uint32_t*)&Ch[(size_t)(row + 8) * ldc + col] =
                    packh2(acc[mt][nt][2] + bb.x, acc[mt][nt][3] + bb.y);
            }
        }
    } else {
        float* Cf = (float*)Cout;
        #pragma unroll
        for (int mt = 0; mt < 4; mt++) {
            const int row = row0 + wr * 64 + mt * 16 + g;
            #pragma unroll
            for (int nt = 0; nt < 8; nt++) {
                const int col = col0 + wc * 64 + nt * 8 + 2 * t;
                float2 bb = *(const float2*)&bias[col];
                float2 v0 = {acc[mt][nt][0] + bb.x, acc[mt][nt][1] + bb.y};
                float2 v1 = {acc[mt][nt][2] + bb.x, acc[mt][nt][3] + bb.y};
                *(float2*)&Cf[(size_t)row * ldc + col]       = v0;
                *(float2*)&Cf[(size_t)(row + 8) * ldc + col] = v1;
            }
        }
    }
}

// ============================ attention (fp16 in/out, R12) =================
#define PADK 36
#define PADV 72
#define PADQ 36
#define ATTN_SMEM ((64*PADK + 32*PADV + 256*PADQ) * 4)   // 55296 bytes

__global__ __launch_bounds__(256, 1) void attn_tc(
    const __half* __restrict__ QKV,
    __half* __restrict__ O)
{
    extern __shared__ uint32_t smu[];
    uint32_t* ksm = smu;
    uint32_t* vsm = smu + 64 * PADK;
    uint32_t* qps = smu + 64 * PADK + 32 * PADV;

    const int tid  = threadIdx.x;
    const int wid  = tid >> 5, lane = tid & 31;
    const int g    = lane >> 2, t = lane & 3;
    const int b    = blockIdx.z;
    const int h    = blockIdx.y;
    const int q0   = blockIdx.x * 256;
    const float C2 = 0.125f * 1.44269504088896340736f;

    const __half* Qh = QKV + ((size_t)b * SEQ + q0) * HID3 + h * HD;
    const __half* Kh = QKV + (size_t)b * SEQ * HID3 + HID + h * HD;
    const __half* Vh = QKV + (size_t)b * SEQ * HID3 + 2 * HID + h * HD;

    {
        const uint4* src = (const uint4*)(Qh + (size_t)tid * HID3);
        uint32_t* dst = qps + tid * PADQ;
        #pragma unroll
        for (int i = 0; i < 8; i++) *(uint4*)(dst + 4 * i) = src[i];
    }
    __syncthreads();

    uint32_t qf[2][4][4];
    #pragma unroll
    for (int mt = 0; mt < 2; mt++) {
        const int r0 = (wid * 32 + mt * 16 + g) * PADQ;
        const int r1 = r0 + 8 * PADQ;
        #pragma unroll
        for (int ks = 0; ks < 4; ks++) {
            qf[mt][ks][0] = qps[r0 + ks * 8 + t    ];
            qf[mt][ks][1] = qps[r1 + ks * 8 + t    ];
            qf[mt][ks][2] = qps[r0 + ks * 8 + t + 4];
            qf[mt][ks][3] = qps[r1 + ks * 8 + t + 4];
        }
    }
    __syncthreads();

    float oacc[2][8][4] = {};
    float m[2][2], l[2][2];
    #pragma unroll
    for (int mt = 0; mt < 2; mt++) {
        m[mt][0] = -1e30f; m[mt][1] = -1e30f;
        l[mt][0] = 0.0f;   l[mt][1] = 0.0f;
    }

    const int jk = tid >> 2, ckb = (tid & 3) * 8;
    const int pv = tid >> 3, db  = (tid & 7) * 8;

    uint32_t* Pw = qps + wid * 32 * PADQ;

    for (int kv0 = 0; kv0 < SEQ; kv0 += 64) {
        __syncthreads();

        {
            const uint4* src = (const uint4*)(Kh + (size_t)(kv0 + jk) * HID3 + ckb * 2);
            *(uint4*)&ksm[jk * PADK + ckb]     = src[0];
            *(uint4*)&ksm[jk * PADK + ckb + 4] = src[1];
        }
        {
            uint4 x = *(const uint4*)(Vh + (size_t)(kv0 + 2 * pv) * HID3 + db);
            uint4 y = *(const uint4*)(Vh + (size_t)(kv0 + 2 * pv + 1) * HID3 + db);
            uint32_t z[8];
            z[0] = prmt(x.x, y.x, 0x5410); z[1] = prmt(x.x, y.x, 0x7632);
            z[2] = prmt(x.y, y.y, 0x5410); z[3] = prmt(x.y, y.y, 0x7632);
            z[4] = prmt(x.z, y.z, 0x5410); z[5] = prmt(x.z, y.z, 0x7632);
            z[6] = prmt(x.w, y.w, 0x5410); z[7] = prmt(x.w, y.w, 0x7632);
            *(uint4*)&vsm[pv * PADV + db]     = *(uint4*)&z[0];
            *(uint4*)&vsm[pv * PADV + db + 4] = *(uint4*)&z[4];
        }
        __syncthreads();

        float s[2][8][4] = {};
        #pragma unroll
        for (int nt = 0; nt < 8; nt++) {
            const uint32_t* kpp = ksm + (nt * 8 + g) * PADK;
            #pragma unroll
            for (int ks = 0; ks < 4; ks++) {
                uint32_t b0 = kpp[ks * 8 + t];
                uint32_t b1 = kpp[ks * 8 + t + 4];
                mma_f16(s[0][nt], qf[0][ks], b0, b1);
                mma_f16(s[1][nt], qf[1][ks], b0, b1);
            }
        }

        #pragma unroll
        for (int mt = 0; mt < 2; mt++) {
            float rm0 = -1e30f, rm1 = -1e30f;
            #pragma unroll
            for (int nt = 0; nt < 8; nt++) {
                rm0 = fmaxf(rm0, fmaxf(s[mt][nt][0], s[mt][nt][1]));
                rm1 = fmaxf(rm1, fmaxf(s[mt][nt][2], s[mt][nt][3]));
            }
            rm0 = fmaxf(rm0, __shfl_xor_sync(0xffffffffu, rm0, 1));
            rm0 = fmaxf(rm0, __shfl_xor_sync(0xffffffffu, rm0, 2));
            rm1 = fmaxf(rm1, __shfl_xor_sync(0xffffffffu, rm1, 1));
            rm1 = fmaxf(rm1, __shfl_xor_sync(0xffffffffu, rm1, 2));

            const float nm0 = fmaxf(m[mt][0], rm0), nm1 = fmaxf(m[mt][1], rm1);
            const float a0 = exp2f((m[mt][0] - nm0) * C2);
            const float a1 = exp2f((m[mt][1] - nm1) * C2);
            const float mc0 = nm0 * C2, mc1 = nm1 * C2;
            float sum0 = 0.0f, sum1 = 0.0f;
            #pragma unroll
            for (int nt = 0; nt < 8; nt++) {
                s[mt][nt][0] = exp2f(fmaf(s[mt][nt][0], C2, -mc0)); sum0 += s[mt][nt][0];
                s[mt][nt][1] = exp2f(fmaf(s[mt][nt][1], C2, -mc0)); sum0 += s[mt][nt][1];
                s[mt][nt][2] = exp2f(fmaf(s[mt][nt][2], C2, -mc1)); sum1 += s[mt][nt][2];
                s[mt][nt][3] = exp2f(fmaf(s[mt][nt][3], C2, -mc1)); sum1 += s[mt][nt][3];
            }
            sum0 += __shfl_xor_sync(0xffffffffu, sum0, 1);
            sum0 += __shfl_xor_sync(0xffffffffu, sum0, 2);
            sum1 += __shfl_xor_sync(0xffffffffu, sum1, 1);
            sum1 += __shfl_xor_sync(0xffffffffu, sum1, 2);

            l[mt][0] = l[mt][0] * a0 + sum0;
            l[mt][1] = l[mt][1] * a1 + sum1;
            m[mt][0] = nm0; m[mt][1] = nm1;
            #pragma unroll
            for (int nt = 0; nt < 8; nt++) {
                oacc[mt][nt][0] *= a0; oacc[mt][nt][1] *= a0;
                oacc[mt][nt][2] *= a1; oacc[mt][nt][3] *= a1;
            }

            #pragma unroll
            for (int nt = 0; nt < 8; nt++) {
                Pw[(mt * 16 + g    ) * PADQ + nt * 4 + t] = packh2(s[mt][nt][0], s[mt][nt][1]);
                Pw[(mt * 16 + g + 8) * PADQ + nt * 4 + t] = packh2(s[mt][nt][2], s[mt][nt][3]);
            }
        }
        __syncwarp();

        #pragma unroll
        for (int ks = 0; ks < 4; ks++) {
            uint32_t af[2][4];
            #pragma unroll
            for (int mt = 0; mt < 2; mt++) {
                const uint32_t* pp = Pw + (mt * 16 + g) * PADQ;
                af[mt][0] = pp[ks * 8 + t];
                af[mt][1] = pp[8 * PADQ + ks * 8 + t];
                af[mt][2] = pp[ks * 8 + t + 4];
                af[mt][3] = pp[8 * PADQ + ks * 8 + t + 4];
            }
            #pragma unroll
            for (int nt = 0; nt < 8; nt++) {
                uint32_t b0 = vsm[(ks * 8 + t    ) * PADV + nt * 8 + g];
                uint32_t b1 = vsm[(ks * 8 + t + 4) * PADV + nt * 8 + g];
                mma_f16(oacc[0][nt], af[0], b0, b1);
                mma_f16(oacc[1][nt], af[1], b0, b1);
            }
        }
        __syncwarp();
    }

    #pragma unroll
    for (int mt = 0; mt < 2; mt++) {
        const float inv0 = 1.0f / l[mt][0], inv1 = 1.0f / l[mt][1];
        __half* Og = O + ((size_t)b * SEQ + q0 + wid * 32 + mt * 16) * HID + h * HD;
        #pragma unroll
        for (int nt = 0; nt < 8; nt++) {
            const int col = nt * 8 + 2 * t;
            *(uint32_t*)&Og[(size_t) g      * HID + col] =
                packh2(oacc[mt][nt][0] * inv0, oacc[mt][nt][1] * inv0);
            *(uint32_t*)&Og[(size_t)(g + 8) * HID + col] =
                packh2(oacc[mt][nt][2] * inv1, oacc[mt][nt][3] * inv1);
        }
    }
}

// ===========================================================================
extern "C" void kernel_launch(void* const* d_in, const int* in_sizes, int n_in,
                              void* d_out, int out_size)
{
    const float* q   = (const float*)d_in[0];
    const float* Wq  = (const float*)d_in[1];
    const float* bq  = (const float*)d_in[2];
    const float* Wkv = (const float*)d_in[3];
    const float* bkv = (const float*)d_in[4];
    const float* Wo  = (const float*)d_in[5];
    const float* bo  = (const float*)d_in[6];
    float* out = (float*)d_out;

    void *pAh, *pWf, *pWoh, *pbf, *pQKV, *pOh;
    cudaGetSymbolAddress(&pAh, g_Ah);
    cudaGetSymbolAddress(&pWf, g_Wf);
    cudaGetSymbolAddress(&pWoh, g_Woh);
    cudaGetSymbolAddress(&pbf, g_bf);
    cudaGetSymbolAddress(&pQKV, g_QKVh);
    cudaGetSymbolAddress(&pOh, g_Oh);
    __half* Ah   = (__half*)pAh;
    __half* Wf   = (__half*)pWf;
    __half* Woh  = (__half*)pWoh;
    float*  bf   = (float*)pbf;
    __half* QKVh = (__half*)pQKV;
    __half* Oh   = (__half*)pOh;

    cudaFuncSetAttribute(gemm_f16, cudaFuncAttributeMaxDynamicSharedMemorySize,
                         GEMM_SMEM);
    cudaFuncSetAttribute(attn_tc, cudaFuncAttributeMaxDynamicSharedMemorySize,
                         ATTN_SMEM);

    // pre-pass
    cvt16<<<MROWS * HID / (256 * 8), 256>>>(q, Ah);
    fuseW<<<HID * HID3 / (256 * 8), 256>>>(Wq, Wkv, bq, bkv, Wf, bf);
    cvt16<<<HID * HID / (256 * 8), 256>>>(Wo, Woh);

    // fused QKV projection: [4096, 3072] fp16, CTA tile 128x128
    gemm_f16<<<dim3(HID3 / 128, MROWS / 128), 128, GEMM_SMEM>>>(
        Ah, HID, Wf, HID3, bf, QKVh, HID3, HID, 1);

    // attention
    dim3 agrid(SEQ / 256, NH, BATCH);
    attn_tc<<<agrid, 256, ATTN_SMEM>>>(QKVh, Oh);

    // output projection: fp32 out
    gemm_f16<<<dim3(HID / 128, MROWS / 128), 128, GEMM_SMEM>>>(
        Oh, HID, Woh, HID, bo, out, HID, HID, 0);
}

// round 15
// speedup vs baseline: 1.1657x; 1.1657x over previous
#include <cuda_runtime.h>
#include <cuda_fp16.h>
#include <cstdint>

// ---------------------------------------------------------------------------
// MHA.  R15: R12 dataflow (proven best) + ldmatrix fragment loads:
// GEMM A-fragments and attention K/P fragments via ldmatrix.m8n8.x4
// (1 instr replaces 4-8 scalar LDS; conflict-free at pad 36).
// ---------------------------------------------------------------------------

#define SEQ     2048
#define BATCH   2
#define NH      16
#define HD      64
#define HID     1024
#define HID3    3072
#define MROWS   (BATCH * SEQ)   // 4096

__device__ __half g_Ah[MROWS * HID];
__device__ __half g_Wf[HID * HID3];
__device__ __half g_Woh[HID * HID];
__device__ float  g_bf[HID3];
__device__ __half g_QKVh[(size_t)MROWS * HID3];
__device__ __half g_Oh[MROWS * HID];

// ------------------------------ helpers ------------------------------------
__device__ __forceinline__ uint32_t packh2(float a, float b) {
    __half2 h = __floats2half2_rn(a, b);
    return *(uint32_t*)&h;
}

__device__ __forceinline__ uint32_t prmt(uint32_t a, uint32_t b, uint32_t s) {
    uint32_t d;
    asm("prmt.b32 %0, %1, %2, %3;" : "=r"(d) : "r"(a), "r"(b), "r"(s));
    return d;
}

__device__ __forceinline__ void mma_f16(float* d, const uint32_t* a,
                                        uint32_t b0, uint32_t b1) {
    asm volatile(
        "mma.sync.aligned.m16n8k16.row.col.f32.f16.f16.f32 "
        "{%0,%1,%2,%3}, {%4,%5,%6,%7}, {%8,%9}, {%0,%1,%2,%3};"
        : "+f"(d[0]), "+f"(d[1]), "+f"(d[2]), "+f"(d[3])
        : "r"(a[0]), "r"(a[1]), "r"(a[2]), "r"(a[3]), "r"(b0), "r"(b1));
}

__device__ __forceinline__ void ldsm_x4(uint32_t& r0, uint32_t& r1,
                                        uint32_t& r2, uint32_t& r3,
                                        uint32_t addr) {
    asm volatile("ldmatrix.sync.aligned.m8n8.x4.shared.b16 {%0,%1,%2,%3}, [%4];"
                 : "=r"(r0), "=r"(r1), "=r"(r2), "=r"(r3) : "r"(addr));
}

// ============================ pre-pass ======================================
__global__ void cvt16(const float* __restrict__ src, __half* __restrict__ dst) {
    size_t i = ((size_t)blockIdx.x * 256 + threadIdx.x) * 8;
    float4 a = *(const float4*)(src + i);
    float4 b = *(const float4*)(src + i + 4);
    uint4 v = {packh2(a.x, a.y), packh2(a.z, a.w),
               packh2(b.x, b.y), packh2(b.z, b.w)};
    *(uint4*)(dst + i) = v;
}

__global__ void fuseW(const float* __restrict__ Wq, const float* __restrict__ Wkv,
                      const float* __restrict__ bq, const float* __restrict__ bkv,
                      __half* __restrict__ Wf, float* __restrict__ bf) {
    int gid = blockIdx.x * 256 + threadIdx.x;
    size_t e = (size_t)gid * 8;
    int r = (int)(e / HID3), c = (int)(e % HID3);
    const float* src = (c < HID) ? Wq + (size_t)r * HID + c
                                 : Wkv + (size_t)r * (2 * HID) + (c - HID);
    float4 a = *(const float4*)src;
    float4 b = *(const float4*)(src + 4);
    uint4 v = {packh2(a.x, a.y), packh2(a.z, a.w),
               packh2(b.x, b.y), packh2(b.z, b.w)};
    *(uint4*)(Wf + e) = v;
    if (gid < HID3 / 8) {
        int cb = gid * 8;
        const float* sb = (cb < HID) ? bq + cb : bkv + (cb - HID);
        *(float4*)(bf + cb)     = *(const float4*)sb;
        *(float4*)(bf + cb + 4) = *(const float4*)(sb + 4);
    }
}

// ============================ fp16 GEMM (R12 + ldmatrix A) ==================
// C[M,N] = A[M,K] @ B[K,N] + bias[N].  128x128x64 tiles, 8 warps (2x4),
// warp tile 64x32.  A smem [m][k2] pad GA=36; B k-pair-interleaved pad GB=136.
#define GA 36
#define GB 136
#define GEMM_SMEM ((2 * (128 * GA + 32 * GB)) * 4)   // 71680 bytes

__global__ __launch_bounds__(256, 2) void gemm_f16(
    const __half* __restrict__ A, int lda,
    const __half* __restrict__ B, int ldb,
    const float* __restrict__ bias,
    void* __restrict__ Cout, int ldc, int K, int fp16out)
{
    extern __shared__ uint32_t smg[];
    uint32_t* Asm = smg;                 // [2][128*GA]
    uint32_t* Bsm = smg + 2 * 128 * GA;  // [2][32*GB]
    const uint32_t smb = (uint32_t)__cvta_generic_to_shared(smg);

    const int tid  = threadIdx.x;
    const int wid  = tid >> 5, lane = tid & 31;
    const int g    = lane >> 2, t = lane & 3;
    const int wr   = wid & 1,  wc = wid >> 1;
    const int row0 = blockIdx.y * 128;
    const int col0 = blockIdx.x * 128;

    // ldmatrix per-lane mapping for A fragments
    const int lrow = lane & 7, lgrp = lane >> 3;
    const int arow = wr * 64 + (lgrp & 1) * 8 + lrow;   // + mt*16
    const int acol = (lgrp >> 1) * 4;                   // + ks*8

    // staging maps
    const int ar = tid >> 1, akb = (tid & 1) * 16;
    const int kp = tid >> 3, nb  = (tid & 7) * 16;

    const __half* Ag = A + (size_t)row0 * lda;
    const __half* Bg = B + col0;

    uint4 ra[4], rbx0, rbx1, rby0, rby1;
    const int NT = K >> 6;

    // ---- prologue: load + stage chunk 0 ----
    #pragma unroll
    for (int i = 0; i < 4; i++)
        ra[i] = *(const uint4*)(Ag + (size_t)ar * lda + akb * 2 + 8 * i);
    {
        const __half* s0 = Bg + (size_t)(2 * kp) * ldb + nb;
        const __half* s1 = s0 + ldb;
        rbx0 = *(const uint4*)s0; rbx1 = *(const uint4*)(s0 + 8);
        rby0 = *(const uint4*)s1; rby1 = *(const uint4*)(s1 + 8);
    }
    {
        *(uint4*)&Asm[ar * GA + akb]      = ra[0];
        *(uint4*)&Asm[ar * GA + akb + 4]  = ra[1];
        *(uint4*)&Asm[ar * GA + akb + 8]  = ra[2];
        *(uint4*)&Asm[ar * GA + akb + 12] = ra[3];
        uint32_t xa[8] = {rbx0.x, rbx0.y, rbx0.z, rbx0.w, rbx1.x, rbx1.y, rbx1.z, rbx1.w};
        uint32_t ya[8] = {rby0.x, rby0.y, rby0.z, rby0.w, rby1.x, rby1.y, rby1.z, rby1.w};
        uint32_t z[16];
        #pragma unroll
        for (int i = 0; i < 8; i++) {
            z[2 * i + 0] = prmt(xa[i], ya[i], 0x5410);
            z[2 * i + 1] = prmt(xa[i], ya[i], 0x7632);
        }
        *(uint4*)&Bsm[kp * GB + nb]      = *(uint4*)&z[0];
        *(uint4*)&Bsm[kp * GB + nb + 4]  = *(uint4*)&z[4];
        *(uint4*)&Bsm[kp * GB + nb + 8]  = *(uint4*)&z[8];
        *(uint4*)&Bsm[kp * GB + nb + 12] = *(uint4*)&z[12];
    }
    __syncthreads();

    float acc[4][4][4] = {};

    for (int kt = 0; kt < NT; kt++) {
        if (kt + 1 < NT) {
            const int kc = (kt + 1) * 64;
            #pragma unroll
            for (int i = 0; i < 4; i++)
                ra[i] = *(const uint4*)(Ag + (size_t)ar * lda + kc + akb * 2 + 8 * i);
            const __half* s0 = Bg + (size_t)(kc + 2 * kp) * ldb + nb;
            const __half* s1 = s0 + ldb;
            rbx0 = *(const uint4*)s0; rbx1 = *(const uint4*)(s0 + 8);
            rby0 = *(const uint4*)s1; rby1 = *(const uint4*)(s1 + 8);
        }

        const uint32_t Aoff = (kt & 1) * 128 * GA;
        const uint32_t* Bc = Bsm + (kt & 1) * 32 * GB;

        #pragma unroll
        for (int ks = 0; ks < 4; ks++) {
            uint32_t af[4][4];
            #pragma unroll
            for (int mt = 0; mt < 4; mt++) {
                const uint32_t addr = smb +
                    (Aoff + (arow + mt * 16) * GA + acol + ks * 8) * 4;
                ldsm_x4(af[mt][0], af[mt][1], af[mt][2], af[mt][3], addr);
            }
            #pragma unroll
            for (int nt = 0; nt < 4; nt++) {
                const int ncol = wc * 32 + nt * 8 + g;
                uint32_t b0 = Bc[(ks * 8 + t    ) * GB + ncol];
                uint32_t b1 = Bc[(ks * 8 + t + 4) * GB + ncol];
                #pragma unroll
                for (int mt = 0; mt < 4; mt++)
                    mma_f16(acc[mt][nt], af[mt], b0, b1);
            }
        }

        if (kt + 1 < NT) {
            uint32_t* Ad = Asm + ((kt + 1) & 1) * 128 * GA;
            uint32_t* Bd = Bsm + ((kt + 1) & 1) * 32 * GB;
            *(uint4*)&Ad[ar * GA + akb]      = ra[0];
            *(uint4*)&Ad[ar * GA + akb + 4]  = ra[1];
            *(uint4*)&Ad[ar * GA + akb + 8]  = ra[2];
            *(uint4*)&Ad[ar * GA + akb + 12] = ra[3];
            uint32_t xa[8] = {rbx0.x, rbx0.y, rbx0.z, rbx0.w, rbx1.x, rbx1.y, rbx1.z, rbx1.w};
            uint32_t ya[8] = {rby0.x, rby0.y, rby0.z, rby0.w, rby1.x, rby1.y, rby1.z, rby1.w};
            uint32_t z[16];
            #pragma unroll
            for (int i = 0; i < 8; i++) {
                z[2 * i + 0] = prmt(xa[i], ya[i], 0x5410);
                z[2 * i + 1] = prmt(xa[i], ya[i], 0x7632);
            }
            *(uint4*)&Bd[kp * GB + nb]      = *(uint4*)&z[0];
            *(uint4*)&Bd[kp * GB + nb + 4]  = *(uint4*)&z[4];
            *(uint4*)&Bd[kp * GB + nb + 8]  = *(uint4*)&z[8];
            *(uint4*)&Bd[kp * GB + nb + 12] = *(uint4*)&z[12];
            __syncthreads();
        }
    }

    // ---- epilogue ----
    if (fp16out) {
        __half* Ch = (__half*)Cout;
        #pragma unroll
        for (int mt = 0; mt < 4; mt++) {
            const int row = row0 + wr * 64 + mt * 16 + g;
            #pragma unroll
            for (int nt = 0; nt < 4; nt++) {
                const int col = col0 + wc * 32 + nt * 8 + 2 * t;
                float2 bb = *(const float2*)&bias[col];
                *(uint32_t*)&Ch[(size_t)row * ldc + col] =
                    packh2(acc[mt][nt][0] + bb.x, acc[mt][nt][1] + bb.y);
                *(uint32_t*)&Ch[(size_t)(row + 8) * ldc + col] =
                    packh2(acc[mt][nt][2] + bb.x, acc[mt][nt][3] + bb.y);
            }
        }
    } else {
        float* Cf = (float*)Cout;
        #pragma unroll
        for (int mt = 0; mt < 4; mt++) {
            const int row = row0 + wr * 64 + mt * 16 + g;
            #pragma unroll
            for (int nt = 0; nt < 4; nt++) {
                const int col = col0 + wc * 32 + nt * 8 + 2 * t;
                float2 bb = *(const float2*)&bias[col];
                float2 v0 = {acc[mt][nt][0] + bb.x, acc[mt][nt][1] + bb.y};
                float2 v1 = {acc[mt][nt][2] + bb.x, acc[mt][nt][3] + bb.y};
                *(float2*)&Cf[(size_t)row * ldc + col]       = v0;
                *(float2*)&Cf[(size_t)(row + 8) * ldc + col] = v1;
            }
        }
    }
}

// ============================ attention (R12 + ldmatrix K/P) ===============
#define PADK 36
#define PADV 72
#define PADQ 36
#define ATTN_SMEM ((64*PADK + 32*PADV + 256*PADQ) * 4)   // 55296 bytes

__global__ __launch_bounds__(256, 1) void attn_tc(
    const __half* __restrict__ QKV,
    __half* __restrict__ O)
{
    extern __shared__ uint32_t smu[];
    uint32_t* ksm = smu;                           // [j][d2] 64 x PADK
    uint32_t* vsm = smu + 64 * PADK;               // [j2][d] 32 x PADV
    uint32_t* qps = smu + 64 * PADK + 32 * PADV;   // Q/P 256 x PADQ
    const uint32_t smb = (uint32_t)__cvta_generic_to_shared(smu);
    const uint32_t qps_off = 64 * PADK + 32 * PADV;

    const int tid  = threadIdx.x;
    const int wid  = tid >> 5, lane = tid & 31;
    const int g    = lane >> 2, t = lane & 3;
    const int b    = blockIdx.z;
    const int h    = blockIdx.y;
    const int q0   = blockIdx.x * 256;
    const float C2 = 0.125f * 1.44269504088896340736f;

    const __half* Qh = QKV + ((size_t)b * SEQ + q0) * HID3 + h * HD;
    const __half* Kh = QKV + (size_t)b * SEQ * HID3 + HID + h * HD;
    const __half* Vh = QKV + (size_t)b * SEQ * HID3 + 2 * HID + h * HD;

    // ldmatrix per-lane mapping
    const int lrow = lane & 7, lgrp = lane >> 3;
    const int kj   = (lgrp >> 1) * 8 + lrow;     // K: + ntp*16
    const int kc4  = (lgrp & 1) * 4;             // K: + ks*8
    const int prw  = (lgrp & 1) * 8 + lrow;      // P: + mt*16 (A-operand order)
    const int pc4  = (lgrp >> 1) * 4;            // P: + ks*8

    // ---- stage Q: raw copy ----
    {
        const uint4* src = (const uint4*)(Qh + (size_t)tid * HID3);
        uint32_t* dst = qps + tid * PADQ;
        #pragma unroll
        for (int i = 0; i < 8; i++) *(uint4*)(dst + 4 * i) = src[i];
    }
    __syncthreads();

    uint32_t qf[2][4][4];
    #pragma unroll
    for (int mt = 0; mt < 2; mt++) {
        const int r0 = (wid * 32 + mt * 16 + g) * PADQ;
        const int r1 = r0 + 8 * PADQ;
        #pragma unroll
        for (int ks = 0; ks < 4; ks++) {
            qf[mt][ks][0] = qps[r0 + ks * 8 + t    ];
            qf[mt][ks][1] = qps[r1 + ks * 8 + t    ];
            qf[mt][ks][2] = qps[r0 + ks * 8 + t + 4];
            qf[mt][ks][3] = qps[r1 + ks * 8 + t + 4];
        }
    }
    __syncthreads();

    float oacc[2][8][4] = {};
    float m[2][2], l[2][2];
    #pragma unroll
    for (int mt = 0; mt < 2; mt++) {
        m[mt][0] = -1e30f; m[mt][1] = -1e30f;
        l[mt][0] = 0.0f;   l[mt][1] = 0.0f;
    }

    const int jk = tid >> 2, ckb = (tid & 3) * 8;
    const int pv = tid >> 3, db  = (tid & 7) * 8;

    uint32_t* Pw = qps + wid * 32 * PADQ;
    const uint32_t pw_off = qps_off + wid * 32 * PADQ;

    for (int kv0 = 0; kv0 < SEQ; kv0 += 64) {
        __syncthreads();

        {
            const uint4* src = (const uint4*)(Kh + (size_t)(kv0 + jk) * HID3 + ckb * 2);
            *(uint4*)&ksm[jk * PADK + ckb]     = src[0];
            *(uint4*)&ksm[jk * PADK + ckb + 4] = src[1];
        }
        {
            uint4 x = *(const uint4*)(Vh + (size_t)(kv0 + 2 * pv) * HID3 + db);
            uint4 y = *(const uint4*)(Vh + (size_t)(kv0 + 2 * pv + 1) * HID3 + db);
            uint32_t z[8];
            z[0] = prmt(x.x, y.x, 0x5410); z[1] = prmt(x.x, y.x, 0x7632);
            z[2] = prmt(x.y, y.y, 0x5410); z[3] = prmt(x.y, y.y, 0x7632);
            z[4] = prmt(x.z, y.z, 0x5410); z[5] = prmt(x.z, y.z, 0x7632);
            z[6] = prmt(x.w, y.w, 0x5410); z[7] = prmt(x.w, y.w, 0x7632);
            *(uint4*)&vsm[pv * PADV + db]     = *(uint4*)&z[0];
            *(uint4*)&vsm[pv * PADV + db + 4] = *(uint4*)&z[4];
        }
        __syncthreads();

        // ---- S = Q K^T : K B-operands via ldmatrix (4 mmas per LDSM) ----
        float s[2][8][4] = {};
        #pragma unroll
        for (int ntp = 0; ntp < 4; ntp++) {
            #pragma unroll
            for (int ks = 0; ks < 4; ks++) {
                uint32_t b0a, b1a, b0b, b1b;
                const uint32_t addr = smb +
                    ((ntp * 16 + kj) * PADK + ks * 8 + kc4) * 4;
                ldsm_x4(b0a, b1a, b0b, b1b, addr);
                mma_f16(s[0][2 * ntp    ], qf[0][ks], b0a, b1a);
                mma_f16(s[1][2 * ntp    ], qf[1][ks], b0a, b1a);
                mma_f16(s[0][2 * ntp + 1], qf[0][ks], b0b, b1b);
                mma_f16(s[1][2 * ntp + 1], qf[1][ks], b0b, b1b);
            }
        }

        // ---- online softmax ----
        #pragma unroll
        for (int mt = 0; mt < 2; mt++) {
            float rm0 = -1e30f, rm1 = -1e30f;
            #pragma unroll
            for (int nt = 0; nt < 8; nt++) {
                rm0 = fmaxf(rm0, fmaxf(s[mt][nt][0], s[mt][nt][1]));
                rm1 = fmaxf(rm1, fmaxf(s[mt][nt][2], s[mt][nt][3]));
            }
            rm0 = fmaxf(rm0, __shfl_xor_sync(0xffffffffu, rm0, 1));
            rm0 = fmaxf(rm0, __shfl_xor_sync(0xffffffffu, rm0, 2));
            rm1 = fmaxf(rm1, __shfl_xor_sync(0xffffffffu, rm1, 1));
            rm1 = fmaxf(rm1, __shfl_xor_sync(0xffffffffu, rm1, 2));

            const float nm0 = fmaxf(m[mt][0], rm0), nm1 = fmaxf(m[mt][1], rm1);
            const float a0 = exp2f((m[mt][0] - nm0) * C2);
            const float a1 = exp2f((m[mt][1] - nm1) * C2);
            const float mc0 = nm0 * C2, mc1 = nm1 * C2;
            float sum0 = 0.0f, sum1 = 0.0f;
            #pragma unroll
            for (int nt = 0; nt < 8; nt++) {
                s[mt][nt][0] = exp2f(fmaf(s[mt][nt][0], C2, -mc0)); sum0 += s[mt][nt][0];
                s[mt][nt][1] = exp2f(fmaf(s[mt][nt][1], C2, -mc0)); sum0 += s[mt][nt][1];
                s[mt][nt][2] = exp2f(fmaf(s[mt][nt][2], C2, -mc1)); sum1 += s[mt][nt][2];
                s[mt][nt][3] = exp2f(fmaf(s[mt][nt][3], C2, -mc1)); sum1 += s[mt][nt][3];
            }
            sum0 += __shfl_xor_sync(0xffffffffu, sum0, 1);
            sum0 += __shfl_xor_sync(0xffffffffu, sum0, 2);
            sum1 += __shfl_xor_sync(0xffffffffu, sum1, 1);
            sum1 += __shfl_xor_sync(0xffffffffu, sum1, 2);

            l[mt][0] = l[mt][0] * a0 + sum0;
            l[mt][1] = l[mt][1] * a1 + sum1;
            m[mt][0] = nm0; m[mt][1] = nm1;
            #pragma unroll
            for (int nt = 0; nt < 8; nt++) {
                oacc[mt][nt][0] *= a0; oacc[mt][nt][1] *= a0;
                oacc[mt][nt][2] *= a1; oacc[mt][nt][3] *= a1;
            }

            #pragma unroll
            for (int nt = 0; nt < 8; nt++) {
                Pw[(mt * 16 + g    ) * PADQ + nt * 4 + t] = packh2(s[mt][nt][0], s[mt][nt][1]);
                Pw[(mt * 16 + g + 8) * PADQ + nt * 4 + t] = packh2(s[mt][nt][2], s[mt][nt][3]);
            }
        }
        __syncwarp();

        // ---- O += P V : P A-fragments via ldmatrix ----
        #pragma unroll
        for (int ks = 0; ks < 4; ks++) {
            uint32_t af[2][4];
            #pragma unroll
            for (int mt = 0; mt < 2; mt++) {
                const uint32_t addr = smb +
                    (pw_off + (mt * 16 + prw) * PADQ + ks * 8 + pc4) * 4;
                ldsm_x4(af[mt][0], af[mt][1], af[mt][2], af[mt][3], addr);
            }
            #pragma unroll
            for (int nt = 0; nt < 8; nt++) {
                uint32_t b0 = vsm[(ks * 8 + t    ) * PADV + nt * 8 + g];
                uint32_t b1 = vsm[(ks * 8 + t + 4) * PADV + nt * 8 + g];
                mma_f16(oacc[0][nt], af[0], b0, b1);
                mma_f16(oacc[1][nt], af[1], b0, b1);
            }
        }
        __syncwarp();
    }

    // ---- epilogue ----
    #pragma unroll
    for (int mt = 0; mt < 2; mt++) {
        const float inv0 = 1.0f / l[mt][0], inv1 = 1.0f / l[mt][1];
        __half* Og = O + ((size_t)b * SEQ + q0 + wid * 32 + mt * 16) * HID + h * HD;
        #pragma unroll
        for (int nt = 0; nt < 8; nt++) {
            const int col = nt * 8 + 2 * t;
            *(uint32_t*)&Og[(size_t) g      * HID + col] =
                packh2(oacc[mt][nt][0] * inv0, oacc[mt][nt][1] * inv0);
            *(uint32_t*)&Og[(size_t)(g + 8) * HID + col] =
                packh2(oacc[mt][nt][2] * inv1, oacc[mt][nt][3] * inv1);
        }
    }
}

// ===========================================================================
extern "C" void kernel_launch(void* const* d_in, const int* in_sizes, int n_in,
                              void* d_out, int out_size)
{
    const float* q   = (const float*)d_in[0];
    const float* Wq  = (const float*)d_in[1];
    const float* bq  = (const float*)d_in[2];
    const float* Wkv = (const float*)d_in[3];
    const float* bkv = (const float*)d_in[4];
    const float* Wo  = (const float*)d_in[5];
    const float* bo  = (const float*)d_in[6];
    float* out = (float*)d_out;

    void *pAh, *pWf, *pWoh, *pbf, *pQKV, *pOh;
    cudaGetSymbolAddress(&pAh, g_Ah);
    cudaGetSymbolAddress(&pWf, g_Wf);
    cudaGetSymbolAddress(&pWoh, g_Woh);
    cudaGetSymbolAddress(&pbf, g_bf);
    cudaGetSymbolAddress(&pQKV, g_QKVh);
    cudaGetSymbolAddress(&pOh, g_Oh);
    __half* Ah   = (__half*)pAh;
    __half* Wf   = (__half*)pWf;
    __half* Woh  = (__half*)pWoh;
    float*  bf   = (float*)pbf;
    __half* QKVh = (__half*)pQKV;
    __half* Oh   = (__half*)pOh;

    cudaFuncSetAttribute(gemm_f16, cudaFuncAttributeMaxDynamicSharedMemorySize,
                         GEMM_SMEM);
    cudaFuncSetAttribute(attn_tc, cudaFuncAttributeMaxDynamicSharedMemorySize,
                         ATTN_SMEM);

    // pre-pass
    cvt16<<<MROWS * HID / (256 * 8), 256>>>(q, Ah);
    fuseW<<<HID * HID3 / (256 * 8), 256>>>(Wq, Wkv, bq, bkv, Wf, bf);
    cvt16<<<HID * HID / (256 * 8), 256>>>(Wo, Woh);

    // fused QKV projection: [4096, 3072] fp16
    gemm_f16<<<dim3(HID3 / 128, MROWS / 128), 256, GEMM_SMEM>>>(
        Ah, HID, Wf, HID3, bf, QKVh, HID3, HID, 1);

    // attention
    dim3 agrid(SEQ / 256, NH, BATCH);
    attn_tc<<<agrid, 256, ATTN_SMEM>>>(QKVh, Oh);

    // output projection: fp32 out
    gemm_f16<<<dim3(HID / 128, MROWS / 128), 256, GEMM_SMEM>>>(
        Oh, HID, Woh, HID, bo, out, HID, HID, 0);
}